// round 2
// baseline (speedup 1.0000x reference)
#include <cuda_runtime.h>

// Upscale2d: 2x zero-insert upsample + 4x4 binomial FIR, reduced to
// separable 2-tap polyphase:
//   even phase: (a + 3b)/4,  odd phase: (3b + c)/4   per axis.
// x: [8,64,256,256] f32 -> y: [8,64,512,512] f32. Zero padding at borders.
//
// Vectorized: each thread owns 4 input columns x 8 input rows.
// Per row: one float4 load + 2 scalar boundary loads; writes 2 float4 per
// output row. 64 threads span the full 256-col width (1024B contiguous).

#define IN_H 256
#define IN_W 256
#define OUT_W 512
#define RPT 8   // input rows per thread

__global__ __launch_bounds__(256) void upscale2d_kernel(
    const float* __restrict__ x, float* __restrict__ y)
{
    const int n4  = threadIdx.x & 63;       // column chunk 0..63 (4 cols each)
    const int sub = threadIdx.x >> 6;       // 0..3: sub row-group within block
    const int g   = blockIdx.x * 4 + sub;   // row group 0..31
    const int p   = blockIdx.y;             // plane (N*C) 0..511

    const int c0 = n4 * 4;
    const float* xp = x + (size_t)p * IN_H * IN_W;
    float*       yp = y + (size_t)p * OUT_W * OUT_W;
    const int r0 = g * RPT;

    float pH[4], pO[4];   // previous row's horizontal pre-combines

    auto loadrow = [&](int r, float* H, float* O) {
        if (r < 0 || r >= IN_H) {
            #pragma unroll
            for (int j = 0; j < 4; j++) { H[j] = 0.f; O[j] = 0.f; }
            return;
        }
        const float* row = xp + (size_t)r * IN_W;
        float4 c = *(const float4*)(row + c0);
        float l  = (c0 > 0)          ? __ldg(row + c0 - 1) : 0.f;
        float rr = (c0 + 4 < IN_W)   ? __ldg(row + c0 + 4) : 0.f;
        H[0] = l   + 3.f * c.x;  O[0] = 3.f * c.x + c.y;
        H[1] = c.x + 3.f * c.y;  O[1] = 3.f * c.y + c.z;
        H[2] = c.y + 3.f * c.z;  O[2] = 3.f * c.z + c.w;
        H[3] = c.z + 3.f * c.w;  O[3] = 3.f * c.w + rr;
    };

    loadrow(r0 - 1, pH, pO);

    #pragma unroll
    for (int i = 0; i <= RPT; i++) {
        const int r = r0 + i;
        float cH[4], cO[4];
        loadrow(r, cH, cO);

        // output row 2r-1: vertical odd phase (3*prev + cur)/4, x 1/4 for 2D
        if (i > 0) {
            float4 v0, v1;
            v0.x = (3.f*pH[0] + cH[0]) * 0.0625f;  v0.y = (3.f*pO[0] + cO[0]) * 0.0625f;
            v0.z = (3.f*pH[1] + cH[1]) * 0.0625f;  v0.w = (3.f*pO[1] + cO[1]) * 0.0625f;
            v1.x = (3.f*pH[2] + cH[2]) * 0.0625f;  v1.y = (3.f*pO[2] + cO[2]) * 0.0625f;
            v1.z = (3.f*pH[3] + cH[3]) * 0.0625f;  v1.w = (3.f*pO[3] + cO[3]) * 0.0625f;
            float* o = yp + (size_t)(2*r - 1) * OUT_W + 2*c0;
            *(float4*)(o)     = v0;
            *(float4*)(o + 4) = v1;
        }
        // output row 2r: vertical even phase (prev + 3*cur)/4
        if (i < RPT) {
            float4 v0, v1;
            v0.x = (pH[0] + 3.f*cH[0]) * 0.0625f;  v0.y = (pO[0] + 3.f*cO[0]) * 0.0625f;
            v0.z = (pH[1] + 3.f*cH[1]) * 0.0625f;  v0.w = (pO[1] + 3.f*cO[1]) * 0.0625f;
            v1.x = (pH[2] + 3.f*cH[2]) * 0.0625f;  v1.y = (pO[2] + 3.f*cO[2]) * 0.0625f;
            v1.z = (pH[3] + 3.f*cH[3]) * 0.0625f;  v1.w = (pO[3] + 3.f*cO[3]) * 0.0625f;
            float* o = yp + (size_t)(2*r) * OUT_W + 2*c0;
            *(float4*)(o)     = v0;
            *(float4*)(o + 4) = v1;
        }
        #pragma unroll
        for (int j = 0; j < 4; j++) { pH[j] = cH[j]; pO[j] = cO[j]; }
    }
}

extern "C" void kernel_launch(void* const* d_in, const int* in_sizes, int n_in,
                              void* d_out, int out_size)
{
    const float* x = (const float*)d_in[0];
    float* y = (float*)d_out;
    int planes = in_sizes[0] / (IN_H * IN_W);          // 512
    dim3 grid(IN_H / (RPT * 4), planes);               // (8, 512)
    upscale2d_kernel<<<grid, 256>>>(x, y);
}

// round 3
// speedup vs baseline: 1.2290x; 1.2290x over previous
#include <cuda_runtime.h>

// Upscale2d: 2x zero-insert upsample + 4x4 binomial FIR == separable 2-tap
// polyphase: even phase (a + 3b)/4, odd phase (3b + c)/4 per axis.
// x: [8,64,256,256] f32 -> y: [8,64,512,512] f32, zero-padded borders.
//
// Each thread owns 2 input columns (float2 load) x RPT input rows (rolling
// vertical window). Horizontal neighbors come from warp shuffles; only
// lanes 0/31 issue a predicated scalar load for the cross-warp element.
// Stores are float4 (streaming), 512B contiguous per warp per output row.

#define IN_H 256
#define IN_W 256
#define OUT_W 512
#define RPT 8   // input rows per thread

__global__ __launch_bounds__(256) void upscale2d_kernel(
    const float* __restrict__ x, float* __restrict__ y)
{
    const int t    = threadIdx.x & 127;        // 0..127: owns cols [2t, 2t+1]
    const int sub  = threadIdx.x >> 7;         // 0..1: row-group within block
    const int g    = blockIdx.x * 2 + sub;     // row group 0..31
    const int p    = blockIdx.y;               // plane (N*C)
    const int lane = threadIdx.x & 31;

    const int c0 = 2 * t;
    const float* xp = x + (size_t)p * IN_H * IN_W;
    float*       yp = y + (size_t)p * OUT_W * OUT_W;
    const int r0 = g * RPT;

    float pH0, pH1, pO0, pO1;   // previous row's horizontal pre-combines

    auto loadrow = [&](int r, float& H0, float& O0, float& H1, float& O1) {
        if (r < 0 || r >= IN_H) { H0 = O0 = H1 = O1 = 0.f; return; }
        const float* row = xp + (size_t)r * IN_W;
        float2 c = *(const float2*)(row + c0);
        // neighbors via shuffle within the warp
        float l  = __shfl_up_sync(0xffffffffu, c.y, 1);   // col c0-1
        float rr = __shfl_down_sync(0xffffffffu, c.x, 1); // col c0+2
        if (lane == 0)  l  = (c0 >= 1)        ? __ldg(row + c0 - 1) : 0.f;
        if (lane == 31) rr = (c0 + 2 < IN_W)  ? __ldg(row + c0 + 2) : 0.f;
        H0 = l   + 3.f * c.x;  O0 = 3.f * c.x + c.y;
        H1 = c.x + 3.f * c.y;  O1 = 3.f * c.y + rr;
    };

    loadrow(r0 - 1, pH0, pO0, pH1, pO1);

    #pragma unroll
    for (int i = 0; i <= RPT; i++) {
        const int r = r0 + i;
        float cH0, cO0, cH1, cO1;
        loadrow(r, cH0, cO0, cH1, cO1);

        // output row 2r-1: vertical odd phase (3*prev + cur), * 1/16 total
        if (i > 0) {
            float4 v;
            v.x = (3.f * pH0 + cH0) * 0.0625f;
            v.y = (3.f * pO0 + cO0) * 0.0625f;
            v.z = (3.f * pH1 + cH1) * 0.0625f;
            v.w = (3.f * pO1 + cO1) * 0.0625f;
            __stcs((float4*)(yp + (size_t)(2 * r - 1) * OUT_W + 2 * c0), v);
        }
        // output row 2r: vertical even phase (prev + 3*cur)
        if (i < RPT) {
            float4 v;
            v.x = (pH0 + 3.f * cH0) * 0.0625f;
            v.y = (pO0 + 3.f * cO0) * 0.0625f;
            v.z = (pH1 + 3.f * cH1) * 0.0625f;
            v.w = (pO1 + 3.f * cO1) * 0.0625f;
            __stcs((float4*)(yp + (size_t)(2 * r) * OUT_W + 2 * c0), v);
        }
        pH0 = cH0; pO0 = cO0; pH1 = cH1; pO1 = cO1;
    }
}

extern "C" void kernel_launch(void* const* d_in, const int* in_sizes, int n_in,
                              void* d_out, int out_size)
{
    const float* x = (const float*)d_in[0];
    float* y = (float*)d_out;
    int planes = in_sizes[0] / (IN_H * IN_W);            // 512
    dim3 grid(IN_H / (RPT * 2), planes);                 // (16, 512)
    upscale2d_kernel<<<grid, 256>>>(x, y);
}

// round 4
// speedup vs baseline: 1.2411x; 1.0098x over previous
#include <cuda_runtime.h>

// Upscale2d: 2x zero-insert upsample + 4x4 binomial FIR == separable 2-tap
// polyphase: even phase (a + 3b)/4, odd phase (3b + c)/4 per axis.
// x: [8,64,256,256] f32 -> y: [8,64,512,512] f32, zero-padded borders.
//
// Each thread owns 2 input columns (float2) x RPT input rows, rolling
// vertical window. Horizontal neighbors via warp shuffle (lanes 0/31 do a
// predicated edge load). Row loads are software-pipelined one iteration
// ahead of the shuffle/fma/store chain. float4 streaming stores: 512B
// contiguous per warp per output row.

#define IN_H 256
#define IN_W 256
#define OUT_W 512
#define RPT 16   // input rows per thread

__global__ __launch_bounds__(256) void upscale2d_kernel(
    const float* __restrict__ x, float* __restrict__ y)
{
    const int t    = threadIdx.x & 127;        // 0..127: owns cols [2t, 2t+1]
    const int sub  = threadIdx.x >> 7;         // 0..1: row-group within block
    const int g    = blockIdx.x * 2 + sub;     // row group
    const int p    = blockIdx.y;               // plane (N*C)
    const int lane = threadIdx.x & 31;

    const int c0 = 2 * t;
    const float* xp = x + (size_t)p * IN_H * IN_W;
    float*       yp = y + (size_t)p * OUT_W * OUT_W;
    const int r0 = g * RPT;

    // raw row load (zero outside [0, IN_H))
    auto loadraw = [&](int r) -> float2 {
        if (r < 0 || r >= IN_H) return make_float2(0.f, 0.f);
        return *(const float2*)(xp + (size_t)r * IN_W + c0);
    };
    // edge element loads for lanes 0/31 (cross-warp neighbor)
    auto loadL = [&](int r) -> float {
        if (r < 0 || r >= IN_H || c0 < 1) return 0.f;
        return __ldg(xp + (size_t)r * IN_W + c0 - 1);
    };
    auto loadR = [&](int r) -> float {
        if (r < 0 || r >= IN_H || c0 + 2 >= IN_W) return 0.f;
        return __ldg(xp + (size_t)r * IN_W + c0 + 2);
    };

    // horizontal pre-combines from a raw row
    auto comb = [&](float2 c, float le, float re,
                    float& H0, float& O0, float& H1, float& O1) {
        float l  = __shfl_up_sync(0xffffffffu, c.y, 1);   // col c0-1
        float rr = __shfl_down_sync(0xffffffffu, c.x, 1); // col c0+2
        if (lane == 0)  l  = le;
        if (lane == 31) rr = re;
        H0 = l   + 3.f * c.x;  O0 = 3.f * c.x + c.y;
        H1 = c.x + 3.f * c.y;  O1 = 3.f * c.y + rr;
    };

    // pipeline: rnext holds raw(r0+i) at the top of iteration i
    float2 rcur  = loadraw(r0 - 1);
    float  lcur  = (lane == 0)  ? loadL(r0 - 1) : 0.f;
    float  rcurE = (lane == 31) ? loadR(r0 - 1) : 0.f;
    float2 rnext = loadraw(r0);
    float  lnext  = (lane == 0)  ? loadL(r0) : 0.f;
    float  rnextE = (lane == 31) ? loadR(r0) : 0.f;

    float pH0, pO0, pH1, pO1;
    comb(rcur, lcur, rcurE, pH0, pO0, pH1, pO1);

    #pragma unroll
    for (int i = 0; i <= RPT; i++) {
        const int r = r0 + i;

        // issue next iteration's load FIRST (latency cover)
        float2 rfut = make_float2(0.f, 0.f);
        float lfut = 0.f, rfutE = 0.f;
        if (i < RPT) {
            rfut = loadraw(r + 1);
            if (lane == 0)  lfut  = loadL(r + 1);
            if (lane == 31) rfutE = loadR(r + 1);
        }

        float cH0, cO0, cH1, cO1;
        comb(rnext, lnext, rnextE, cH0, cO0, cH1, cO1);

        // output row 2r-1: vertical odd phase (3*prev + cur) * 1/16
        if (i > 0) {
            float4 v;
            v.x = (3.f * pH0 + cH0) * 0.0625f;
            v.y = (3.f * pO0 + cO0) * 0.0625f;
            v.z = (3.f * pH1 + cH1) * 0.0625f;
            v.w = (3.f * pO1 + cO1) * 0.0625f;
            __stcs((float4*)(yp + (size_t)(2 * r - 1) * OUT_W + 2 * c0), v);
        }
        // output row 2r: vertical even phase (prev + 3*cur) * 1/16
        if (i < RPT) {
            float4 v;
            v.x = (pH0 + 3.f * cH0) * 0.0625f;
            v.y = (pO0 + 3.f * cO0) * 0.0625f;
            v.z = (pH1 + 3.f * cH1) * 0.0625f;
            v.w = (pO1 + 3.f * cO1) * 0.0625f;
            __stcs((float4*)(yp + (size_t)(2 * r) * OUT_W + 2 * c0), v);
        }

        pH0 = cH0; pO0 = cO0; pH1 = cH1; pO1 = cO1;
        rnext = rfut; lnext = lfut; rnextE = rfutE;
    }
}

extern "C" void kernel_launch(void* const* d_in, const int* in_sizes, int n_in,
                              void* d_out, int out_size)
{
    const float* x = (const float*)d_in[0];
    float* y = (float*)d_out;
    int planes = in_sizes[0] / (IN_H * IN_W);            // 512
    dim3 grid(IN_H / (RPT * 2), planes);                 // (8, 512)
    upscale2d_kernel<<<grid, 256>>>(x, y);
}

// round 5
// speedup vs baseline: 1.2463x; 1.0042x over previous
#include <cuda_runtime.h>

// Upscale2d: 2x zero-insert upsample + 4x4 binomial FIR == separable 2-tap
// polyphase: even phase (a + 3b)/4, odd phase (3b + c)/4 per axis.
// x: [8,64,256,256] f32 -> y: [8,64,512,512] f32, zero-padded borders.
//
// Each thread owns 2 input columns (float2) x RPT=8 input rows (rolling
// vertical window). Horizontal neighbors via warp shuffle (lanes 0/31 do a
// predicated edge load). Row loads software-pipelined one iteration ahead.
// float4 streaming stores: 512B contiguous per warp per output row.
// RPT=8 keeps the grid at 8192 CTAs for high occupancy + latency cover.

#define IN_H 256
#define IN_W 256
#define OUT_W 512
#define RPT 8   // input rows per thread

__global__ __launch_bounds__(256) void upscale2d_kernel(
    const float* __restrict__ x, float* __restrict__ y)
{
    const int t    = threadIdx.x & 127;        // 0..127: owns cols [2t, 2t+1]
    const int sub  = threadIdx.x >> 7;         // 0..1: row-group within block
    const int g    = blockIdx.x * 2 + sub;     // row group
    const int p    = blockIdx.y;               // plane (N*C)
    const int lane = threadIdx.x & 31;

    const int c0 = 2 * t;
    const float* xp = x + (size_t)p * IN_H * IN_W;
    float*       yp = y + (size_t)p * OUT_W * OUT_W;
    const int r0 = g * RPT;

    const bool edgeL = (lane == 0)  && (c0 >= 1);
    const bool edgeR = (lane == 31) && (c0 + 2 < IN_W);

    // raw row load (zero outside [0, IN_H)); e = cross-warp edge element
    auto loadraw = [&](int r, float& e) -> float2 {
        e = 0.f;
        if (r < 0 || r >= IN_H) return make_float2(0.f, 0.f);
        const float* row = xp + (size_t)r * IN_W;
        if (edgeL) e = __ldg(row + c0 - 1);
        if (edgeR) e = __ldg(row + c0 + 2);
        return *(const float2*)(row + c0);
    };

    // horizontal pre-combines
    auto comb = [&](float2 c, float e,
                    float& H0, float& O0, float& H1, float& O1) {
        float l  = __shfl_up_sync(0xffffffffu, c.y, 1);   // col c0-1
        float rr = __shfl_down_sync(0xffffffffu, c.x, 1); // col c0+2
        if (lane == 0)  l  = e;
        if (lane == 31) rr = e;
        H0 = l   + 3.f * c.x;  O0 = 3.f * c.x + c.y;
        H1 = c.x + 3.f * c.y;  O1 = 3.f * c.y + rr;
    };

    float eP, eN;
    float2 rprev = loadraw(r0 - 1, eP);
    float2 rnext = loadraw(r0, eN);

    float pH0, pO0, pH1, pO1;
    comb(rprev, eP, pH0, pO0, pH1, pO1);

    #pragma unroll
    for (int i = 0; i <= RPT; i++) {
        const int r = r0 + i;

        // issue next iteration's load FIRST (latency cover)
        float eF = 0.f;
        float2 rfut = make_float2(0.f, 0.f);
        if (i < RPT) rfut = loadraw(r + 1, eF);

        float cH0, cO0, cH1, cO1;
        comb(rnext, eN, cH0, cO0, cH1, cO1);

        // output row 2r-1: vertical odd phase (3*prev + cur) * 1/16
        if (i > 0) {
            float4 v;
            v.x = (3.f * pH0 + cH0) * 0.0625f;
            v.y = (3.f * pO0 + cO0) * 0.0625f;
            v.z = (3.f * pH1 + cH1) * 0.0625f;
            v.w = (3.f * pO1 + cO1) * 0.0625f;
            __stcs((float4*)(yp + (size_t)(2 * r - 1) * OUT_W + 2 * c0), v);
        }
        // output row 2r: vertical even phase (prev + 3*cur) * 1/16
        if (i < RPT) {
            float4 v;
            v.x = (pH0 + 3.f * cH0) * 0.0625f;
            v.y = (pO0 + 3.f * cO0) * 0.0625f;
            v.z = (pH1 + 3.f * cH1) * 0.0625f;
            v.w = (pO1 + 3.f * cO1) * 0.0625f;
            __stcs((float4*)(yp + (size_t)(2 * r) * OUT_W + 2 * c0), v);
        }

        pH0 = cH0; pO0 = cO0; pH1 = cH1; pO1 = cO1;
        rnext = rfut; eN = eF;
    }
}

extern "C" void kernel_launch(void* const* d_in, const int* in_sizes, int n_in,
                              void* d_out, int out_size)
{
    const float* x = (const float*)d_in[0];
    float* y = (float*)d_out;
    int planes = in_sizes[0] / (IN_H * IN_W);            // 512
    dim3 grid(IN_H / (RPT * 2), planes);                 // (16, 512)
    upscale2d_kernel<<<grid, 256>>>(x, y);
}